// round 10
// baseline (speedup 1.0000x reference)
#include <cuda_runtime.h>
#include <cuda_bf16.h>
#include <math_constants.h>

// Problem constants
#define N_TOK     16384
#define D_MODEL   2048
#define N_EXP     64
#define TOPK      4

// Output layout (fp32 elements)
#define OFF_TOPK_I  0
#define OFF_TOPK_S  (N_TOK * TOPK)                 // 65536
#define OFF_SCORES  (2 * N_TOK * TOPK)             // 131072
#define OFF_AUX     (OFF_SCORES + N_TOK * N_EXP)   // 1179648

// GEMM tiling
#define TILE_M   128
#define NTILES   (N_TOK / TILE_M)   // 128 token tiles
#define KSPLIT   2
#define KHALF    (D_MODEL / KSPLIT) // 1024
#define KC       16
#define NC       (KHALF / KC)       // 64 chunks per half
#define UPAD     20
#define NTHR     256

// ---- packed f32x2 helpers (sm_103a SASS FFMA2; bit-exact fp32 pairs) ----
#define PACK_DUP(d, x)     asm("mov.b64 %0, {%1, %1};" : "=l"(d) : "f"(x))
#define UNPACK2(lo, hi, v) asm("mov.b64 {%0, %1}, %2;" : "=f"(lo), "=f"(hi) : "l"(v))
#define FMA2(d, a, b)      asm("fma.rn.f32x2 %0, %1, %2, %0;" : "+l"(d) : "l"(a), "l"(b))

__device__ float g_partial[KSPLIT * N_TOK * N_EXP];   // 8MB scratch: [half][token][expert]
__device__ float g_expert_sum[N_EXP];                 // zero at load; reset by aux kernel

// ================= K1: partial GEMM, 256 thr/CTA, 2 CTAs/SM =================
struct SmemG {
    float us[2][TILE_M][UPAD];    // [buf][token][k]
    float es[2][KC][N_EXP];       // [buf][k][expert]
};

__global__ void __launch_bounds__(NTHR, 2)
router_gemm_kernel(const float* __restrict__ u,
                   const float* __restrict__ E) {
    __shared__ SmemG sm;

    const int tid  = threadIdx.x;
    const int tx   = tid & 7;     // experts tx*8 .. tx*8+7
    const int ty   = tid >> 3;    // tokens ty + 32*i, i=0..3
    const int tile = blockIdx.x & (NTILES - 1);
    const int half = blockIdx.x >> 7;
    const int row0 = tile * TILE_M;
    const int kb0  = half * KHALF;

    unsigned long long acc2[4][4];
#pragma unroll
    for (int i = 0; i < 4; i++)
#pragma unroll
        for (int p = 0; p < 4; p++) acc2[i][p] = 0ULL;

    // loader mapping (256 threads)
    const int u_lm  = tid >> 2;          // 0..63 (rows u_lm, u_lm+64)
    const int u_lk4 = tid & 3;           // float4 within 16-k chunk
    const int e_le4 = tid & 15;          // float4 within 64-expert row
    const int e_lk  = tid >> 4;          // 0..15 (one k row)

    // prologue: chunk 0 -> buf 0
    {
#pragma unroll
        for (int r = 0; r < 2; r++) {
            int m = u_lm + 64 * r;
            float4 v = *reinterpret_cast<const float4*>(
                &u[(size_t)(row0 + m) * D_MODEL + kb0 + u_lk4 * 4]);
            *reinterpret_cast<float4*>(&sm.us[0][m][u_lk4 * 4]) = v;
        }
        float4 v = *reinterpret_cast<const float4*>(
            &E[(size_t)(kb0 + e_lk) * N_EXP + e_le4 * 4]);
        *reinterpret_cast<float4*>(&sm.es[0][e_lk][e_le4 * 4]) = v;
    }
    __syncthreads();

    int buf = 0;
    for (int c = 0; c < NC; c++) {
        float4 ru[2], re;
        const bool more = (c + 1 < NC);
        if (more) {
            const int kbase = kb0 + (c + 1) * KC;
#pragma unroll
            for (int r = 0; r < 2; r++) {
                int m = u_lm + 64 * r;
                ru[r] = *reinterpret_cast<const float4*>(
                    &u[(size_t)(row0 + m) * D_MODEL + kbase + u_lk4 * 4]);
            }
            re = *reinterpret_cast<const float4*>(
                &E[(size_t)(kbase + e_lk) * N_EXP + e_le4 * 4]);
        }

#pragma unroll
        for (int k = 0; k < KC; k++) {
            ulonglong2 bv0 = *reinterpret_cast<const ulonglong2*>(&sm.es[buf][k][tx * 8]);
            ulonglong2 bv1 = *reinterpret_cast<const ulonglong2*>(&sm.es[buf][k][tx * 8 + 4]);

            unsigned long long ap[4];
#pragma unroll
            for (int i = 0; i < 4; i++) {
                float a = sm.us[buf][ty + 32 * i][k];
                PACK_DUP(ap[i], a);
            }
#pragma unroll
            for (int i = 0; i < 4; i++) {
                FMA2(acc2[i][0], ap[i], bv0.x);
                FMA2(acc2[i][1], ap[i], bv0.y);
                FMA2(acc2[i][2], ap[i], bv1.x);
                FMA2(acc2[i][3], ap[i], bv1.y);
            }
        }

        if (more) {
            int nb = buf ^ 1;
#pragma unroll
            for (int r = 0; r < 2; r++) {
                int m = u_lm + 64 * r;
                *reinterpret_cast<float4*>(&sm.us[nb][m][u_lk4 * 4]) = ru[r];
            }
            *reinterpret_cast<float4*>(&sm.es[nb][e_lk][e_le4 * 4]) = re;
        }
        __syncthreads();
        buf ^= 1;
    }

    // write partial logits (no bias) to scratch
    float* dst = &g_partial[(size_t)half * (N_TOK * N_EXP)];
#pragma unroll
    for (int i = 0; i < 4; i++) {
        int m = ty + 32 * i;
#pragma unroll
        for (int p = 0; p < 4; p++) {
            float lo, hi;
            UNPACK2(lo, hi, acc2[i][p]);
            *reinterpret_cast<float2*>(&dst[(size_t)(row0 + m) * N_EXP + tx * 8 + 2 * p])
                = make_float2(lo, hi);
        }
    }
}

// ================= K2: combine + softmax + top4 + scores + expert sums =================
__global__ void __launch_bounds__(128, 1)
router_epi_kernel(const float* __restrict__ bias,
                  float* __restrict__ out) {
    __shared__ float scores_s[TILE_M][N_EXP + 1];
    __shared__ float csum[TILE_M];
    __shared__ float bias_s[N_EXP];

    const int tid  = threadIdx.x;
    const int row0 = blockIdx.x * TILE_M;
    const int t    = tid;
    const int gt   = row0 + t;

    if (tid < N_EXP) bias_s[tid] = bias[tid];
    __syncthreads();

    // combine k-halves + bias -> per-thread logit row in registers
    float lr[N_EXP];
    {
        const float* p0 = &g_partial[(size_t)gt * N_EXP];
        const float* p1 = &g_partial[(size_t)(N_TOK * N_EXP) + (size_t)gt * N_EXP];
#pragma unroll
        for (int j = 0; j < N_EXP / 4; j++) {
            float4 a = *reinterpret_cast<const float4*>(&p0[j * 4]);
            float4 b = *reinterpret_cast<const float4*>(&p1[j * 4]);
            lr[j * 4 + 0] = a.x + b.x + bias_s[j * 4 + 0];
            lr[j * 4 + 1] = a.y + b.y + bias_s[j * 4 + 1];
            lr[j * 4 + 2] = a.z + b.z + bias_s[j * 4 + 2];
            lr[j * 4 + 3] = a.w + b.w + bias_s[j * 4 + 3];
        }
    }

    // stable top-4 (strict >, lower index wins ties)
    float v0 = -CUDART_INF_F, v1 = -CUDART_INF_F, v2 = -CUDART_INF_F, v3 = -CUDART_INF_F;
    int   i0 = 0, i1 = 0, i2 = 0, i3 = 0;
#pragma unroll
    for (int e = 0; e < N_EXP; e++) {
        float l = lr[e];
        if (l > v3) {
            if (l > v0)      { v3 = v2; i3 = i2; v2 = v1; i2 = i1; v1 = v0; i1 = i0; v0 = l; i0 = e; }
            else if (l > v1) { v3 = v2; i3 = i2; v2 = v1; i2 = i1; v1 = l; i1 = e; }
            else if (l > v2) { v3 = v2; i3 = i2; v2 = l;  i2 = e; }
            else             { v3 = l;  i3 = e; }
        }
    }
    const float mx = v0;
    float ssum = 0.0f;
#pragma unroll
    for (int e = 0; e < N_EXP; e++) {
        float ex = __expf(lr[e] - mx);
        ssum += ex;
        lr[e] = ex;
    }
    const float rs = 1.0f / ssum;

    out[OFF_TOPK_I + gt * 4 + 0] = (float)i0;
    out[OFF_TOPK_I + gt * 4 + 1] = (float)i1;
    out[OFF_TOPK_I + gt * 4 + 2] = (float)i2;
    out[OFF_TOPK_I + gt * 4 + 3] = (float)i3;
    out[OFF_TOPK_S + gt * 4 + 0] = lr[i0] * rs;
    out[OFF_TOPK_S + gt * 4 + 1] = lr[i1] * rs;
    out[OFF_TOPK_S + gt * 4 + 2] = lr[i2] * rs;
    out[OFF_TOPK_S + gt * 4 + 3] = lr[i3] * rs;

    // final scores to smem (for coalesced store + column sums)
#pragma unroll
    for (int e = 0; e < N_EXP; e++) scores_s[t][e] = lr[e] * rs;
    __syncthreads();

    // coalesced scores store + per-expert partial sums
    {
        float cs = 0.0f;
        const int base = blockIdx.x * (TILE_M * N_EXP);
#pragma unroll 8
        for (int it = 0; it < (TILE_M * N_EXP) / TILE_M; it++) {
            int idx = it * TILE_M + tid;
            int tt  = idx >> 6;
            int ee  = idx & 63;
            float val = scores_s[tt][ee];
            out[OFF_SCORES + base + idx] = val;
            cs += val;
        }
        csum[tid] = cs;
        __syncthreads();
        if (tid < N_EXP)
            atomicAdd(&g_expert_sum[tid], csum[tid] + csum[tid + 64]);
    }
}

// ================= K3: aux loss + reset (graph-replay safe) =================
__global__ void __launch_bounds__(64, 1)
router_aux_kernel(float* __restrict__ out) {
    __shared__ float p[N_EXP];
    int e = threadIdx.x;
    float m = g_expert_sum[e] * (1.0f / (float)N_TOK);
    p[e] = m * m;
    g_expert_sum[e] = 0.0f;     // reset for next graph replay
    __syncthreads();
    if (e == 0) {
        float s = 0.0f;
#pragma unroll
        for (int i = 0; i < N_EXP; i++) s += p[i];
        out[OFF_AUX] = s * (float)N_EXP;
    }
}

extern "C" void kernel_launch(void* const* d_in, const int* in_sizes, int n_in,
                              void* d_out, int out_size) {
    const float* u    = (const float*)d_in[0];
    const float* E    = (const float*)d_in[1];
    const float* bias = (const float*)d_in[2];
    float* out = (float*)d_out;

    router_gemm_kernel<<<NTILES * KSPLIT, NTHR>>>(u, E);
    router_epi_kernel<<<NTILES, 128>>>(bias, out);
    router_aux_kernel<<<1, 64>>>(out);
}

// round 11
// speedup vs baseline: 1.3955x; 1.3955x over previous
#include <cuda_runtime.h>
#include <cuda_bf16.h>
#include <math_constants.h>

// Problem constants
#define N_TOK     16384
#define D_MODEL   2048
#define N_EXP     64
#define TOPK      4

// Output layout (fp32 elements)
#define OFF_TOPK_I  0
#define OFF_TOPK_S  (N_TOK * TOPK)                 // 65536
#define OFF_SCORES  (2 * N_TOK * TOPK)             // 131072
#define OFF_AUX     (OFF_SCORES + N_TOK * N_EXP)   // 1179648

// GEMM tiling (round-2 proven configuration)
#define TILE_M  128
#define KC      16
#define NC      (D_MODEL / KC)    // 128 chunks
#define UPAD    20

// ---- packed f32x2 helpers (sm_103a) ----
#define PACK_DUP(d, x)     asm("mov.b64 %0, {%1, %1};" : "=l"(d) : "f"(x))
#define UNPACK2(lo, hi, v) asm("mov.b64 {%0, %1}, %2;" : "=f"(lo), "=f"(hi) : "l"(v))
#define FMA2(d, a, b)      asm("fma.rn.f32x2 %0, %1, %2, %0;" : "+l"(d) : "l"(a), "l"(b))

__device__ float g_expert_sum[N_EXP];

struct SmemG {
    float us[2][TILE_M][UPAD];    // [buf][token][k]
    float es[2][KC][N_EXP];       // [buf][k][expert]
};
struct SmemE {
    float logits[TILE_M][N_EXP + 1];
    float rsum[TILE_M];
    float csum[TILE_M];
};
union __align__(16) Smem {
    SmemG g;
    SmemE e;
};

__global__ void __launch_bounds__(128, 1)
router_zero_kernel() {
    g_expert_sum[threadIdx.x & 63] = 0.0f;
}

__global__ void __launch_bounds__(128, 1)
router_main_kernel(const float* __restrict__ u,
                   const float* __restrict__ E,
                   const float* __restrict__ bias,
                   float* __restrict__ out) {
    __shared__ Smem sm;

    const int tid = threadIdx.x;
    const int tx  = tid & 7;     // experts tx*8 .. tx*8+7
    const int ty  = tid >> 3;    // tokens ty + 16*i, i=0..7
    const int row0 = blockIdx.x * TILE_M;

    unsigned long long acc2[8][4];
#pragma unroll
    for (int i = 0; i < 8; i++)
#pragma unroll
        for (int p = 0; p < 4; p++) acc2[i][p] = 0ULL;

    float bj[8];
#pragma unroll
    for (int j = 0; j < 8; j++) bj[j] = __ldg(&bias[tx * 8 + j]);

    // loader mapping
    const int u_lm  = tid >> 2;          // 0..31
    const int u_lk4 = tid & 3;
    const int e_le4 = tid & 15;
    const int e_lk  = tid >> 4;          // 0..7

    // ---- prologue: load chunk 0 into buf 0 ----
    {
#pragma unroll
        for (int r = 0; r < 4; r++) {
            int m = u_lm + 32 * r;
            float4 v = *reinterpret_cast<const float4*>(
                &u[(size_t)(row0 + m) * D_MODEL + u_lk4 * 4]);
            *reinterpret_cast<float4*>(&sm.g.us[0][m][u_lk4 * 4]) = v;
        }
#pragma unroll
        for (int rr = 0; rr < 2; rr++) {
            int k = e_lk + 8 * rr;
            float4 v = *reinterpret_cast<const float4*>(
                &E[(size_t)k * N_EXP + e_le4 * 4]);
            *reinterpret_cast<float4*>(&sm.g.es[0][k][e_le4 * 4]) = v;
        }
    }
    __syncthreads();

    int buf = 0;
    for (int c = 0; c < NC; c++) {
        // ---- issue global loads for chunk c+1 into registers ----
        float4 ru[4], re[2];
        const bool more = (c + 1 < NC);
        if (more) {
            const int kbase = (c + 1) * KC;
#pragma unroll
            for (int r = 0; r < 4; r++) {
                int m = u_lm + 32 * r;
                ru[r] = *reinterpret_cast<const float4*>(
                    &u[(size_t)(row0 + m) * D_MODEL + kbase + u_lk4 * 4]);
            }
#pragma unroll
            for (int rr = 0; rr < 2; rr++) {
                int k = e_lk + 8 * rr;
                re[rr] = *reinterpret_cast<const float4*>(
                    &E[(size_t)(kbase + k) * N_EXP + e_le4 * 4]);
            }
        }

        // ---- compute chunk c: k processed in PAIRS for 2x independent FMA span ----
#pragma unroll
        for (int k = 0; k < KC; k += 2) {
            // fragments for k and k+1 (12 LDS + 16 dup-MOVs), then 32 independent FMA2
            ulonglong2 b0v0 = *reinterpret_cast<const ulonglong2*>(&sm.g.es[buf][k][tx * 8]);
            ulonglong2 b0v1 = *reinterpret_cast<const ulonglong2*>(&sm.g.es[buf][k][tx * 8 + 4]);
            ulonglong2 b1v0 = *reinterpret_cast<const ulonglong2*>(&sm.g.es[buf][k + 1][tx * 8]);
            ulonglong2 b1v1 = *reinterpret_cast<const ulonglong2*>(&sm.g.es[buf][k + 1][tx * 8 + 4]);

            unsigned long long a0[8], a1[8];
#pragma unroll
            for (int i = 0; i < 8; i++) {
                float x0 = sm.g.us[buf][ty + 16 * i][k];
                float x1 = sm.g.us[buf][ty + 16 * i][k + 1];
                PACK_DUP(a0[i], x0);
                PACK_DUP(a1[i], x1);
            }
            // FMA order per accumulator: k then k+1 -> summation order identical to r2
#pragma unroll
            for (int i = 0; i < 8; i++) {
                FMA2(acc2[i][0], a0[i], b0v0.x);
                FMA2(acc2[i][1], a0[i], b0v0.y);
                FMA2(acc2[i][2], a0[i], b0v1.x);
                FMA2(acc2[i][3], a0[i], b0v1.y);
            }
#pragma unroll
            for (int i = 0; i < 8; i++) {
                FMA2(acc2[i][0], a1[i], b1v0.x);
                FMA2(acc2[i][1], a1[i], b1v0.y);
                FMA2(acc2[i][2], a1[i], b1v1.x);
                FMA2(acc2[i][3], a1[i], b1v1.y);
            }
        }

        // ---- store staged registers into the other buffer ----
        if (more) {
            int nb = buf ^ 1;
#pragma unroll
            for (int r = 0; r < 4; r++) {
                int m = u_lm + 32 * r;
                *reinterpret_cast<float4*>(&sm.g.us[nb][m][u_lk4 * 4]) = ru[r];
            }
#pragma unroll
            for (int rr = 0; rr < 2; rr++) {
                int k = e_lk + 8 * rr;
                *reinterpret_cast<float4*>(&sm.g.es[nb][k][e_le4 * 4]) = re[rr];
            }
        }
        __syncthreads();
        buf ^= 1;
    }

    // ================= epilogue =================
#pragma unroll
    for (int i = 0; i < 8; i++) {
        int m = ty + 16 * i;
#pragma unroll
        for (int p = 0; p < 4; p++) {
            float lo, hi;
            UNPACK2(lo, hi, acc2[i][p]);
            sm.e.logits[m][tx * 8 + 2 * p]     = lo + bj[2 * p];
            sm.e.logits[m][tx * 8 + 2 * p + 1] = hi + bj[2 * p + 1];
        }
    }
    __syncthreads();

    // per-token softmax + stable top-4 (one thread per token)
    {
        const int t  = tid;
        const int gt = row0 + t;

        float v0 = -CUDART_INF_F, v1 = -CUDART_INF_F, v2 = -CUDART_INF_F, v3 = -CUDART_INF_F;
        int   i0 = 0, i1 = 0, i2 = 0, i3 = 0;
#pragma unroll 8
        for (int e = 0; e < N_EXP; e++) {
            float l = sm.e.logits[t][e];
            if (l > v3) {
                if (l > v0)      { v3 = v2; i3 = i2; v2 = v1; i2 = i1; v1 = v0; i1 = i0; v0 = l; i0 = e; }
                else if (l > v1) { v3 = v2; i3 = i2; v2 = v1; i2 = i1; v1 = l; i1 = e; }
                else if (l > v2) { v3 = v2; i3 = i2; v2 = l;  i2 = e; }
                else             { v3 = l;  i3 = e; }
            }
        }
        const float mx = v0;
        float s = 0.0f;
#pragma unroll 8
        for (int e = 0; e < N_EXP; e++) {
            float ex = __expf(sm.e.logits[t][e] - mx);
            s += ex;
            sm.e.logits[t][e] = ex;
        }
        const float rs = 1.0f / s;
        sm.e.rsum[t] = rs;

        out[OFF_TOPK_I + gt * 4 + 0] = (float)i0;
        out[OFF_TOPK_I + gt * 4 + 1] = (float)i1;
        out[OFF_TOPK_I + gt * 4 + 2] = (float)i2;
        out[OFF_TOPK_I + gt * 4 + 3] = (float)i3;
        out[OFF_TOPK_S + gt * 4 + 0] = sm.e.logits[t][i0] * rs;
        out[OFF_TOPK_S + gt * 4 + 1] = sm.e.logits[t][i1] * rs;
        out[OFF_TOPK_S + gt * 4 + 2] = sm.e.logits[t][i2] * rs;
        out[OFF_TOPK_S + gt * 4 + 3] = sm.e.logits[t][i3] * rs;
    }
    __syncthreads();

    // coalesced scores store + per-expert partial sums
    {
        float csum = 0.0f;
        const int base = blockIdx.x * (TILE_M * N_EXP);
#pragma unroll 4
        for (int it = 0; it < (TILE_M * N_EXP) / 128; it++) {
            int idx = it * 128 + tid;
            int t   = idx >> 6;
            int e   = idx & 63;
            float val = sm.e.logits[t][e] * sm.e.rsum[t];
            out[OFF_SCORES + base + idx] = val;
            csum += val;
        }
        sm.e.csum[tid] = csum;
        __syncthreads();
        if (tid < N_EXP)
            atomicAdd(&g_expert_sum[tid], sm.e.csum[tid] + sm.e.csum[tid + 64]);
    }
}

__global__ void __launch_bounds__(64, 1)
router_aux_kernel(float* __restrict__ out) {
    __shared__ float p[N_EXP];
    int e = threadIdx.x;
    float m = g_expert_sum[e] * (1.0f / (float)N_TOK);
    p[e] = m * m;
    __syncthreads();
    if (e == 0) {
        float s = 0.0f;
#pragma unroll
        for (int i = 0; i < N_EXP; i++) s += p[i];
        out[OFF_AUX] = s * (float)N_EXP;
    }
}

extern "C" void kernel_launch(void* const* d_in, const int* in_sizes, int n_in,
                              void* d_out, int out_size) {
    const float* u    = (const float*)d_in[0];
    const float* E    = (const float*)d_in[1];
    const float* bias = (const float*)d_in[2];
    float* out = (float*)d_out;

    router_zero_kernel<<<1, 64>>>();
    router_main_kernel<<<N_TOK / TILE_M, 128>>>(u, E, bias, out);
    router_aux_kernel<<<1, 64>>>(out);
}